// round 6
// baseline (speedup 1.0000x reference)
#include <cuda_runtime.h>
#include <cuda_bf16.h>
#include <cstdint>

#define BATCH   32768
#define NSITES  64
#define NBULK   62
#define TPB     128
#define SAMP_CTA 64                    // 4 warps x 16 samples
#define NCTA    (BATCH / SAMP_CTA)     // 512
#define ROWB    80                     // bytes per SMEM tile row (32 bf16 + 8 pad)
#define TILE_BYTES (32 * ROWB)         // 2560
#define SITE_BYTES (4 * TILE_BYTES)    // M0h, M0l, Dh, Dl = 10240
#define NBUF    4

// Precomputed bf16 hi/lo tiles per site: M0 (hi,lo) and Delta=M1-M0 (hi,lo)
__device__ __align__(256) unsigned char g_btiles[NBULK * SITE_BYTES];

// ---------------- helpers ----------------
__device__ __forceinline__ uint32_t smem_u32(const void* p) {
    uint32_t a;
    asm("{ .reg .u64 t; cvta.to.shared.u64 t, %1; cvt.u32.u64 %0, t; }" : "=r"(a) : "l"(p));
    return a;
}
__device__ __forceinline__ void cp_async16(uint32_t dst, const void* src) {
    asm volatile("cp.async.ca.shared.global [%0], [%1], 16;" :: "r"(dst), "l"(src));
}
__device__ __forceinline__ void cp_commit() { asm volatile("cp.async.commit_group;"); }
template<int N> __device__ __forceinline__ void cp_wait() { asm volatile("cp.async.wait_group %0;" :: "n"(N)); }

__device__ __forceinline__ void ldsm_x4(uint32_t* r, uint32_t addr) {
    asm volatile("ldmatrix.sync.aligned.m8n8.x4.shared.b16 {%0,%1,%2,%3}, [%4];"
        : "=r"(r[0]), "=r"(r[1]), "=r"(r[2]), "=r"(r[3]) : "r"(addr));
}
__device__ __forceinline__ void mma16816(float* d, const uint32_t* a, uint32_t b0, uint32_t b1) {
    asm volatile("mma.sync.aligned.m16n8k16.row.col.f32.bf16.bf16.f32 "
        "{%0,%1,%2,%3}, {%4,%5,%6,%7}, {%8,%9}, {%0,%1,%2,%3};"
        : "+f"(d[0]), "+f"(d[1]), "+f"(d[2]), "+f"(d[3])
        : "r"(a[0]), "r"(a[1]), "r"(a[2]), "r"(a[3]), "r"(b0), "r"(b1));
}
__device__ __forceinline__ uint32_t packbf(float lo, float hi) {
    uint32_t r;
    asm("cvt.rn.bf16x2.f32 %0, %1, %2;" : "=r"(r) : "f"(hi), "f"(lo));
    return r;
}

// ---------------- prep: fp32 bulk -> bf16 hi/lo tiles of M0 and Delta=M1-M0 ----------------
__global__ void prep_kernel(const float* __restrict__ bulk) {
    int s = blockIdx.x;
    const float* base = bulk + s * 2048;            // [d][c][e]
    for (int idx = threadIdx.x; idx < 4096; idx += blockDim.x) {
        int t    = idx >> 10;                        // 0=M0h 1=M0l 2=Dh 3=Dl
        int half = t & 1;
        int rem  = idx & 1023;
        int n    = rem >> 5;                         // e
        int k    = rem & 31;                         // d
        float m0 = base[(k * 2 + 0) * 32 + n];
        float m1 = base[(k * 2 + 1) * 32 + n];
        float x  = (t >> 1) ? (m1 - m0) : m0;
        __nv_bfloat16 bh = __float2bfloat16(x);
        __nv_bfloat16 v  = half ? __float2bfloat16(x - __bfloat162float(bh)) : bh;
        *(__nv_bfloat16*)(g_btiles + (size_t)s * SITE_BYTES + t * TILE_BYTES + n * ROWB + k * 2) = v;
    }
}

// ---------------- main kernel ----------------
// One m16 tile per warp (16 samples). 4 warps/CTA -> 64 samples/CTA, 512 CTAs.
__global__ void __launch_bounds__(TPB, 4)
mps_mma_kernel(const int*   __restrict__ conf,
               const float* __restrict__ left,
               const float* __restrict__ right,
               float*       __restrict__ out)
{
    __shared__ __align__(16) unsigned char sb[NBUF][SITE_BYTES];
    __shared__ unsigned long long masks_s[SAMP_CTA];
    __shared__ float lt_s[64];
    __shared__ float rt_s[64];

    const int tid  = threadIdx.x;
    const int wid  = tid >> 5;
    const int lane = tid & 31;
    const int rowq = lane >> 2;       // 0..7
    const int q    = lane & 3;        // 0..3

    if (tid < 64) { lt_s[tid] = left[tid]; rt_s[tid] = right[tid]; }

    // per-sample config bitmask (64 samples, threads 0..63)
    if (tid < SAMP_CTA) {
        unsigned long long mask = 0;
        const int4* cp4 = (const int4*)(conf + (size_t)(blockIdx.x * SAMP_CTA + tid) * NSITES);
        #pragma unroll
        for (int i = 0; i < NSITES / 4; i++) {
            int4 v = cp4[i];
            mask |= ((unsigned long long)(v.x & 1) << (4 * i))
                  | ((unsigned long long)(v.y & 1) << (4 * i + 1))
                  | ((unsigned long long)(v.z & 1) << (4 * i + 2))
                  | ((unsigned long long)(v.w & 1) << (4 * i + 3));
        }
        masks_s[tid] = mask;
    }

    // prefetch sites 0 and 1
    #pragma unroll
    for (int p = 0; p < 2; p++) {
        uint32_t dst = smem_u32(&sb[p][0]);
        const unsigned char* src = g_btiles + (size_t)p * SITE_BYTES;
        #pragma unroll
        for (int i = 0; i < 5; i++)
            cp_async16(dst + (tid + i * TPB) * 16, src + (tid + i * TPB) * 16);
        cp_commit();
    }
    __syncthreads();   // masks_s, lt_s, rt_s visible

    // masks of this thread's 2 rows (rowq, rowq+8 of the warp's 16 samples)
    unsigned long long mrA = masks_s[wid * 16 + rowq];
    unsigned long long mrB = masks_s[wid * 16 + rowq + 8];

    // ---- initial env = left[c0] as bf16 hi/lo A fragments ----
    // ah/al[kt][reg]: even reg -> row rowq (mrA), odd -> rowq+8 (mrB)
    // reg pair (2h,2h+1) covers k0 = 16*kt + 8*h + 2q
    uint32_t ah[2][4], al[2][4];
    {
        const int cA = (int)(mrA & 1ull);
        const int cB = (int)(mrB & 1ull);
        #pragma unroll
        for (int kt = 0; kt < 2; kt++)
            #pragma unroll
            for (int h = 0; h < 2; h++) {
                int k0 = 16 * kt + 8 * h + 2 * q;
                float xA0 = lt_s[cA * 32 + k0], xA1 = lt_s[cA * 32 + k0 + 1];
                float xB0 = lt_s[cB * 32 + k0], xB1 = lt_s[cB * 32 + k0 + 1];
                uint32_t hA = packbf(xA0, xA1);
                uint32_t hB = packbf(xB0, xB1);
                __nv_bfloat162 bA = *(__nv_bfloat162*)&hA;
                __nv_bfloat162 bB = *(__nv_bfloat162*)&hB;
                ah[kt][2 * h]     = hA;
                ah[kt][2 * h + 1] = hB;
                al[kt][2 * h]     = packbf(xA0 - __bfloat162float(bA.x),
                                           xA1 - __bfloat162float(bA.y));
                al[kt][2 * h + 1] = packbf(xB0 - __bfloat162float(bB.x),
                                           xB1 - __bfloat162float(bB.y));
            }
    }

    const uint32_t lds_off = (uint32_t)((lane & 7) * ROWB + (lane >> 3) * 16);
    float acc[4][4];   // [ntile j][reg]

    for (int s = 0; s < NBULK; s++) {
        // distance-2 prefetch into 4-deep ring
        if (s + 2 < NBULK) {
            uint32_t dst = smem_u32(&sb[(s + 2) & 3][0]);
            const unsigned char* src = g_btiles + (size_t)(s + 2) * SITE_BYTES;
            #pragma unroll
            for (int i = 0; i < 5; i++)
                cp_async16(dst + (tid + i * TPB) * 16, src + (tid + i * TPB) * 16);
            cp_commit();
            cp_wait<2>();
        } else if (s + 1 < NBULK) {
            cp_wait<1>();
        } else {
            cp_wait<0>();
        }
        __syncthreads();   // single barrier per site: publish site-s tiles

        #pragma unroll
        for (int j = 0; j < 4; j++)
            #pragma unroll
            for (int r = 0; r < 4; r++) acc[j][r] = 0.0f;

        const uint32_t sbase = smem_u32(&sb[s & 3][0]);

        // ---- pass 1: acc += E * M0 (3 precision terms) ----
        #pragma unroll
        for (int j = 0; j < 4; j++) {
            uint32_t bh[4], bl[4];
            ldsm_x4(bh, sbase + 0 * TILE_BYTES + (uint32_t)(8 * j) * ROWB + lds_off);
            ldsm_x4(bl, sbase + 1 * TILE_BYTES + (uint32_t)(8 * j) * ROWB + lds_off);
            float* a = acc[j];
            mma16816(a, ah[0], bh[0], bh[1]);
            mma16816(a, ah[1], bh[2], bh[3]);
            mma16816(a, al[0], bh[0], bh[1]);
            mma16816(a, al[1], bh[2], bh[3]);
            mma16816(a, ah[0], bl[0], bl[1]);
            mma16816(a, ah[1], bl[2], bl[3]);
        }

        // ---- mask A fragments in place with site-(s+1) bits ----
        {
            const uint32_t cA = (uint32_t)((mrA >> (s + 1)) & 1ull);
            const uint32_t cB = (uint32_t)((mrB >> (s + 1)) & 1ull);
            #pragma unroll
            for (int kt = 0; kt < 2; kt++)
                #pragma unroll
                for (int h = 0; h < 2; h++) {
                    ah[kt][2*h]   = cA ? ah[kt][2*h]   : 0u;
                    al[kt][2*h]   = cA ? al[kt][2*h]   : 0u;
                    ah[kt][2*h+1] = cB ? ah[kt][2*h+1] : 0u;
                    al[kt][2*h+1] = cB ? al[kt][2*h+1] : 0u;
                }
        }

        // ---- pass 2: acc += E_masked * Delta (3 precision terms) ----
        #pragma unroll
        for (int j = 0; j < 4; j++) {
            uint32_t bh[4], bl[4];
            ldsm_x4(bh, sbase + 2 * TILE_BYTES + (uint32_t)(8 * j) * ROWB + lds_off);
            ldsm_x4(bl, sbase + 3 * TILE_BYTES + (uint32_t)(8 * j) * ROWB + lds_off);
            float* a = acc[j];
            mma16816(a, ah[0], bh[0], bh[1]);
            mma16816(a, ah[1], bh[2], bh[3]);
            mma16816(a, al[0], bh[0], bh[1]);
            mma16816(a, al[1], bh[2], bh[3]);
            mma16816(a, ah[0], bl[0], bl[1]);
            mma16816(a, ah[1], bl[2], bl[3]);
        }

        // ---- split selected env (acc) -> next A fragments (D-layout == A-layout) ----
        if (s + 1 < NBULK) {
            #pragma unroll
            for (int kt = 0; kt < 2; kt++)
                #pragma unroll
                for (int h = 0; h < 2; h++) {
                    float x0 = acc[2 * kt + h][0], x1 = acc[2 * kt + h][1];
                    float x2 = acc[2 * kt + h][2], x3 = acc[2 * kt + h][3];
                    uint32_t h01 = packbf(x0, x1);
                    uint32_t h23 = packbf(x2, x3);
                    __nv_bfloat162 b01 = *(__nv_bfloat162*)&h01;
                    __nv_bfloat162 b23 = *(__nv_bfloat162*)&h23;
                    ah[kt][2 * h]     = h01;
                    ah[kt][2 * h + 1] = h23;
                    al[kt][2 * h]     = packbf(x0 - __bfloat162float(b01.x),
                                               x1 - __bfloat162float(b01.y));
                    al[kt][2 * h + 1] = packbf(x2 - __bfloat162float(b23.x),
                                               x3 - __bfloat162float(b23.y));
                }
        }
        // no trailing barrier: 4-deep ring + distance-2 prefetch safe under 1-site skew
    }

    // ---- final dot with right[:, c63]; reduce across the 4 lanes of each row group ----
    {
        const int cA = (int)(mrA >> 63);
        const int cB = (int)(mrB >> 63);
        float pa = 0.0f, pb = 0.0f;
        #pragma unroll
        for (int j = 0; j < 4; j++) {
            int n0 = 8 * j + 2 * q;
            pa += acc[j][0] * rt_s[n0 * 2 + cA] + acc[j][1] * rt_s[(n0 + 1) * 2 + cA];
            pb += acc[j][2] * rt_s[n0 * 2 + cB] + acc[j][3] * rt_s[(n0 + 1) * 2 + cB];
        }
        pa += __shfl_xor_sync(0xFFFFFFFF, pa, 1);
        pa += __shfl_xor_sync(0xFFFFFFFF, pa, 2);
        pb += __shfl_xor_sync(0xFFFFFFFF, pb, 1);
        pb += __shfl_xor_sync(0xFFFFFFFF, pb, 2);
        if (q == 0) {
            int base = blockIdx.x * SAMP_CTA + wid * 16 + rowq;
            out[base]     = pa;
            out[base + 8] = pb;
        }
    }
}

extern "C" void kernel_launch(void* const* d_in, const int* in_sizes, int n_in,
                              void* d_out, int out_size) {
    const int*   conf  = (const int*)d_in[0];
    const float* left  = (const float*)d_in[1];
    const float* bulk  = (const float*)d_in[2];
    const float* right = (const float*)d_in[3];
    float*       out   = (float*)d_out;

    prep_kernel<<<NBULK, 256>>>(bulk);
    mps_mma_kernel<<<NCTA, TPB>>>(conf, left, right, out);
}

// round 7
// speedup vs baseline: 1.0448x; 1.0448x over previous
#include <cuda_runtime.h>
#include <cuda_bf16.h>
#include <cstdint>

#define BATCH   32768
#define NSITES  64
#define NBULK   62
#define TPB     128
#define SAMP_CTA 128                   // 4 warps x 32 samples
#define NCTA    (BATCH / SAMP_CTA)     // 256
#define ROWB    80                     // bytes per SMEM tile row (32 bf16 + 8 pad)
#define TILE_BYTES (32 * ROWB)         // 2560
#define SITE_BYTES (4 * TILE_BYTES)    // M0h, M0l, Dh, Dl = 10240
#define NBUF    4
#define RING_BYTES (NBUF * SITE_BYTES) // 40960
#define SMEM_TOTAL (2 * RING_BYTES + SAMP_CTA * 8 + 2 * 64 * 4)  // 83456

// Precomputed bf16 hi/lo tiles per site: M0 (hi,lo) and Delta=M1-M0 (hi,lo)
__device__ __align__(256) unsigned char g_btiles[NBULK * SITE_BYTES];

// ---------------- helpers ----------------
__device__ __forceinline__ uint32_t smem_u32(const void* p) {
    uint32_t a;
    asm("{ .reg .u64 t; cvta.to.shared.u64 t, %1; cvt.u32.u64 %0, t; }" : "=r"(a) : "l"(p));
    return a;
}
__device__ __forceinline__ void cp_async16(uint32_t dst, const void* src) {
    asm volatile("cp.async.ca.shared.global [%0], [%1], 16;" :: "r"(dst), "l"(src));
}
__device__ __forceinline__ void cp_commit() { asm volatile("cp.async.commit_group;"); }
template<int N> __device__ __forceinline__ void cp_wait() { asm volatile("cp.async.wait_group %0;" :: "n"(N)); }
__device__ __forceinline__ void pair_bar(int id) {
    asm volatile("bar.sync %0, 64;" :: "r"(id) : "memory");
}
__device__ __forceinline__ void ldsm_x4(uint32_t* r, uint32_t addr) {
    asm volatile("ldmatrix.sync.aligned.m8n8.x4.shared.b16 {%0,%1,%2,%3}, [%4];"
        : "=r"(r[0]), "=r"(r[1]), "=r"(r[2]), "=r"(r[3]) : "r"(addr));
}
__device__ __forceinline__ void mma16816(float* d, const uint32_t* a, uint32_t b0, uint32_t b1) {
    asm volatile("mma.sync.aligned.m16n8k16.row.col.f32.bf16.bf16.f32 "
        "{%0,%1,%2,%3}, {%4,%5,%6,%7}, {%8,%9}, {%0,%1,%2,%3};"
        : "+f"(d[0]), "+f"(d[1]), "+f"(d[2]), "+f"(d[3])
        : "r"(a[0]), "r"(a[1]), "r"(a[2]), "r"(a[3]), "r"(b0), "r"(b1));
}
__device__ __forceinline__ uint32_t packbf(float lo, float hi) {
    uint32_t r;
    asm("cvt.rn.bf16x2.f32 %0, %1, %2;" : "=r"(r) : "f"(hi), "f"(lo));
    return r;
}

// ---------------- prep: fp32 bulk -> bf16 hi/lo tiles of M0 and Delta=M1-M0 ----------------
__global__ void prep_kernel(const float* __restrict__ bulk) {
    int s = blockIdx.x;
    const float* base = bulk + s * 2048;            // [d][c][e]
    for (int idx = threadIdx.x; idx < 4096; idx += blockDim.x) {
        int t    = idx >> 10;                        // 0=M0h 1=M0l 2=Dh 3=Dl
        int half = t & 1;
        int rem  = idx & 1023;
        int n    = rem >> 5;                         // e
        int k    = rem & 31;                         // d
        float m0 = base[(k * 2 + 0) * 32 + n];
        float m1 = base[(k * 2 + 1) * 32 + n];
        float x  = (t >> 1) ? (m1 - m0) : m0;
        __nv_bfloat16 bh = __float2bfloat16(x);
        __nv_bfloat16 v  = half ? __float2bfloat16(x - __bfloat162float(bh)) : bh;
        *(__nv_bfloat16*)(g_btiles + (size_t)s * SITE_BYTES + t * TILE_BYTES + n * ROWB + k * 2) = v;
    }
}

// ---------------- main kernel ----------------
// M=32 per warp; warp PAIRS share a private 4-deep SMEM ring, synced by named barriers.
__global__ void __launch_bounds__(TPB, 2)
mps_mma_kernel(const int*   __restrict__ conf,
               const float* __restrict__ left,
               const float* __restrict__ right,
               float*       __restrict__ out)
{
    extern __shared__ __align__(16) unsigned char dsm[];
    const int tid  = threadIdx.x;
    const int wid  = tid >> 5;
    const int lane = tid & 31;
    const int rowq = lane >> 2;       // 0..7
    const int q    = lane & 3;        // 0..3
    const int ring = wid >> 1;        // 0 or 1
    const int bid  = 1 + ring;        // named barrier id
    const int ptid = tid & 63;        // thread id within pair

    unsigned char* rbuf = dsm + ring * RING_BYTES;
    unsigned long long* masks_s = (unsigned long long*)(dsm + 2 * RING_BYTES);
    float* lt_s = (float*)(dsm + 2 * RING_BYTES + SAMP_CTA * 8);
    float* rt_s = lt_s + 64;

    if (tid < 64) { lt_s[tid] = left[tid]; rt_s[tid] = right[tid]; }

    // per-sample config bitmask
    {
        unsigned long long mask = 0;
        const int4* cp4 = (const int4*)(conf + (size_t)(blockIdx.x * SAMP_CTA + tid) * NSITES);
        #pragma unroll
        for (int i = 0; i < NSITES / 4; i++) {
            int4 v = cp4[i];
            mask |= ((unsigned long long)(v.x & 1) << (4 * i))
                  | ((unsigned long long)(v.y & 1) << (4 * i + 1))
                  | ((unsigned long long)(v.z & 1) << (4 * i + 2))
                  | ((unsigned long long)(v.w & 1) << (4 * i + 3));
        }
        masks_s[tid] = mask;
    }

    // pair-private prefetch of sites 0 and 1 (10 chunks of 16B per thread per site)
    #pragma unroll
    for (int p = 0; p < 2; p++) {
        uint32_t dst = smem_u32(rbuf + p * SITE_BYTES);
        const unsigned char* src = g_btiles + (size_t)p * SITE_BYTES;
        #pragma unroll
        for (int i = 0; i < 10; i++)
            cp_async16(dst + (ptid + i * 64) * 16, src + (ptid + i * 64) * 16);
        cp_commit();
    }
    __syncthreads();   // masks_s, lt_s, rt_s visible (once)

    // masks of this thread's 4 rows (warp's 32 samples: rowq, +8, +16, +24)
    unsigned long long mr[4];
    #pragma unroll
    for (int k = 0; k < 4; k++) mr[k] = masks_s[wid * 32 + rowq + 8 * k];

    // ---- initial env = left[c0] as bf16 hi/lo A fragments ----
    // ah/al[i][kt][reg]: even reg -> row rowq+16i (mr[2i]), odd -> rowq+16i+8 (mr[2i+1])
    uint32_t ah[2][2][4], al[2][2][4];
    #pragma unroll
    for (int i = 0; i < 2; i++) {
        const int cA = (int)(mr[2 * i] & 1ull);
        const int cB = (int)(mr[2 * i + 1] & 1ull);
        #pragma unroll
        for (int kt = 0; kt < 2; kt++)
            #pragma unroll
            for (int h = 0; h < 2; h++) {
                int k0 = 16 * kt + 8 * h + 2 * q;
                float xA0 = lt_s[cA * 32 + k0], xA1 = lt_s[cA * 32 + k0 + 1];
                float xB0 = lt_s[cB * 32 + k0], xB1 = lt_s[cB * 32 + k0 + 1];
                uint32_t hA = packbf(xA0, xA1);
                uint32_t hB = packbf(xB0, xB1);
                __nv_bfloat162 bA = *(__nv_bfloat162*)&hA;
                __nv_bfloat162 bB = *(__nv_bfloat162*)&hB;
                ah[i][kt][2 * h]     = hA;
                ah[i][kt][2 * h + 1] = hB;
                al[i][kt][2 * h]     = packbf(xA0 - __bfloat162float(bA.x),
                                              xA1 - __bfloat162float(bA.y));
                al[i][kt][2 * h + 1] = packbf(xB0 - __bfloat162float(bB.x),
                                              xB1 - __bfloat162float(bB.y));
            }
    }

    const uint32_t lds_off = (uint32_t)((lane & 7) * ROWB + (lane >> 3) * 16);
    float acc[2][4][4];

    for (int s = 0; s < NBULK; s++) {
        // pair-private distance-2 prefetch into 4-deep ring
        if (s + 2 < NBULK) {
            uint32_t dst = smem_u32(rbuf + ((s + 2) & 3) * SITE_BYTES);
            const unsigned char* src = g_btiles + (size_t)(s + 2) * SITE_BYTES;
            #pragma unroll
            for (int i = 0; i < 10; i++)
                cp_async16(dst + (ptid + i * 64) * 16, src + (ptid + i * 64) * 16);
            cp_commit();
            cp_wait<2>();
        } else if (s + 1 < NBULK) {
            cp_wait<1>();
        } else {
            cp_wait<0>();
        }
        pair_bar(bid);     // only the 2 warps of this pair synchronize

        #pragma unroll
        for (int i = 0; i < 2; i++)
            #pragma unroll
            for (int j = 0; j < 4; j++)
                #pragma unroll
                for (int r = 0; r < 4; r++) acc[i][j][r] = 0.0f;

        const uint32_t sbase = smem_u32(rbuf + (s & 3) * SITE_BYTES);

        // ---- pass 1: acc += E * M0 (3 precision terms) ----
        #pragma unroll
        for (int j = 0; j < 4; j++) {
            uint32_t bh[4], bl[4];
            ldsm_x4(bh, sbase + 0 * TILE_BYTES + (uint32_t)(8 * j) * ROWB + lds_off);
            ldsm_x4(bl, sbase + 1 * TILE_BYTES + (uint32_t)(8 * j) * ROWB + lds_off);
            #pragma unroll
            for (int i = 0; i < 2; i++) {
                float* a = acc[i][j];
                mma16816(a, ah[i][0], bh[0], bh[1]);
                mma16816(a, ah[i][1], bh[2], bh[3]);
                mma16816(a, al[i][0], bh[0], bh[1]);
                mma16816(a, al[i][1], bh[2], bh[3]);
                mma16816(a, ah[i][0], bl[0], bl[1]);
                mma16816(a, ah[i][1], bl[2], bl[3]);
            }
        }

        // ---- mask A fragments in place with site-(s+1) bits ----
        {
            const uint32_t c0 = (uint32_t)((mr[0] >> (s + 1)) & 1ull);
            const uint32_t c1 = (uint32_t)((mr[1] >> (s + 1)) & 1ull);
            const uint32_t c2 = (uint32_t)((mr[2] >> (s + 1)) & 1ull);
            const uint32_t c3 = (uint32_t)((mr[3] >> (s + 1)) & 1ull);
            #pragma unroll
            for (int kt = 0; kt < 2; kt++)
                #pragma unroll
                for (int h = 0; h < 2; h++) {
                    ah[0][kt][2*h]   = c0 ? ah[0][kt][2*h]   : 0u;
                    al[0][kt][2*h]   = c0 ? al[0][kt][2*h]   : 0u;
                    ah[0][kt][2*h+1] = c1 ? ah[0][kt][2*h+1] : 0u;
                    al[0][kt][2*h+1] = c1 ? al[0][kt][2*h+1] : 0u;
                    ah[1][kt][2*h]   = c2 ? ah[1][kt][2*h]   : 0u;
                    al[1][kt][2*h]   = c2 ? al[1][kt][2*h]   : 0u;
                    ah[1][kt][2*h+1] = c3 ? ah[1][kt][2*h+1] : 0u;
                    al[1][kt][2*h+1] = c3 ? al[1][kt][2*h+1] : 0u;
                }
        }

        // ---- pass 2: acc += E_masked * Delta (3 precision terms) ----
        #pragma unroll
        for (int j = 0; j < 4; j++) {
            uint32_t bh[4], bl[4];
            ldsm_x4(bh, sbase + 2 * TILE_BYTES + (uint32_t)(8 * j) * ROWB + lds_off);
            ldsm_x4(bl, sbase + 3 * TILE_BYTES + (uint32_t)(8 * j) * ROWB + lds_off);
            #pragma unroll
            for (int i = 0; i < 2; i++) {
                float* a = acc[i][j];
                mma16816(a, ah[i][0], bh[0], bh[1]);
                mma16816(a, ah[i][1], bh[2], bh[3]);
                mma16816(a, al[i][0], bh[0], bh[1]);
                mma16816(a, al[i][1], bh[2], bh[3]);
                mma16816(a, ah[i][0], bl[0], bl[1]);
                mma16816(a, ah[i][1], bl[2], bl[3]);
            }
        }

        // ---- split selected env (acc) -> next A fragments (D-layout == A-layout) ----
        if (s + 1 < NBULK) {
            #pragma unroll
            for (int i = 0; i < 2; i++)
                #pragma unroll
                for (int kt = 0; kt < 2; kt++)
                    #pragma unroll
                    for (int h = 0; h < 2; h++) {
                        float x0 = acc[i][2 * kt + h][0], x1 = acc[i][2 * kt + h][1];
                        float x2 = acc[i][2 * kt + h][2], x3 = acc[i][2 * kt + h][3];
                        uint32_t h01 = packbf(x0, x1);
                        uint32_t h23 = packbf(x2, x3);
                        __nv_bfloat162 b01 = *(__nv_bfloat162*)&h01;
                        __nv_bfloat162 b23 = *(__nv_bfloat162*)&h23;
                        ah[i][kt][2 * h]     = h01;
                        ah[i][kt][2 * h + 1] = h23;
                        al[i][kt][2 * h]     = packbf(x0 - __bfloat162float(b01.x),
                                                      x1 - __bfloat162float(b01.y));
                        al[i][kt][2 * h + 1] = packbf(x2 - __bfloat162float(b23.x),
                                                      x3 - __bfloat162float(b23.y));
                    }
        }
        // no trailing barrier: 4-deep ring + distance-2 prefetch safe under 1-site pair skew
    }

    // ---- final dot with right[:, c63]; reduce across the 4 lanes of each row group ----
    float p[4];
    #pragma unroll
    for (int i = 0; i < 2; i++) {
        const int cA = (int)(mr[2 * i]     >> 63);
        const int cB = (int)(mr[2 * i + 1] >> 63);
        float pa = 0.0f, pb = 0.0f;
        #pragma unroll
        for (int j = 0; j < 4; j++) {
            int n0 = 8 * j + 2 * q;
            pa += acc[i][j][0] * rt_s[n0 * 2 + cA] + acc[i][j][1] * rt_s[(n0 + 1) * 2 + cA];
            pb += acc[i][j][2] * rt_s[n0 * 2 + cB] + acc[i][j][3] * rt_s[(n0 + 1) * 2 + cB];
        }
        p[2 * i]     = pa;
        p[2 * i + 1] = pb;
    }
    #pragma unroll
    for (int k = 0; k < 4; k++) {
        p[k] += __shfl_xor_sync(0xFFFFFFFF, p[k], 1);
        p[k] += __shfl_xor_sync(0xFFFFFFFF, p[k], 2);
    }
    if (q == 0) {
        int base = blockIdx.x * SAMP_CTA + wid * 32 + rowq;
        #pragma unroll
        for (int k = 0; k < 4; k++) out[base + 8 * k] = p[k];
    }
}

extern "C" void kernel_launch(void* const* d_in, const int* in_sizes, int n_in,
                              void* d_out, int out_size) {
    const int*   conf  = (const int*)d_in[0];
    const float* left  = (const float*)d_in[1];
    const float* bulk  = (const float*)d_in[2];
    const float* right = (const float*)d_in[3];
    float*       out   = (float*)d_out;

    cudaFuncSetAttribute(mps_mma_kernel,
                         cudaFuncAttributeMaxDynamicSharedMemorySize, SMEM_TOTAL);
    prep_kernel<<<NBULK, 256>>>(bulk);
    mps_mma_kernel<<<NCTA, TPB, SMEM_TOTAL>>>(conf, left, right, out);
}

// round 8
// speedup vs baseline: 1.0746x; 1.0285x over previous
#include <cuda_runtime.h>
#include <cuda_bf16.h>
#include <cstdint>

#define BATCH   32768
#define NSITES  64
#define NBULK   62
#define NHALF   31                     // sites per half-chain
#define TPB     128
#define SAMP_CTA 64                    // 2 L-warps x 32 samples (+ 2 R-warps, same samples)
#define NCTA    (BATCH / SAMP_CTA)     // 512
#define ROWB    80                     // bytes per SMEM tile row (32 bf16 + 8 pad)
#define TILE_BYTES (32 * ROWB)         // 2560
#define SITE_BYTES (4 * TILE_BYTES)    // M0h, M0l, Dh, Dl = 10240
#define NBUF    2

// bf16 hi/lo tiles per site: normal (left chain) and transposed (right chain)
__device__ __align__(256) unsigned char g_btiles [NBULK * SITE_BYTES];
__device__ __align__(256) unsigned char g_btilesT[NBULK * SITE_BYTES];

// ---------------- helpers ----------------
__device__ __forceinline__ uint32_t smem_u32(const void* p) {
    uint32_t a;
    asm("{ .reg .u64 t; cvta.to.shared.u64 t, %1; cvt.u32.u64 %0, t; }" : "=r"(a) : "l"(p));
    return a;
}
__device__ __forceinline__ void cp_async16(uint32_t dst, const void* src) {
    asm volatile("cp.async.ca.shared.global [%0], [%1], 16;" :: "r"(dst), "l"(src));
}
__device__ __forceinline__ void cp_commit() { asm volatile("cp.async.commit_group;"); }
template<int N> __device__ __forceinline__ void cp_wait() { asm volatile("cp.async.wait_group %0;" :: "n"(N)); }
__device__ __forceinline__ void pair_bar(int id) {
    asm volatile("bar.sync %0, 64;" :: "r"(id) : "memory");
}
__device__ __forceinline__ void ldsm_x4(uint32_t* r, uint32_t addr) {
    asm volatile("ldmatrix.sync.aligned.m8n8.x4.shared.b16 {%0,%1,%2,%3}, [%4];"
        : "=r"(r[0]), "=r"(r[1]), "=r"(r[2]), "=r"(r[3]) : "r"(addr));
}
__device__ __forceinline__ void mma16816(float* d, const uint32_t* a, uint32_t b0, uint32_t b1) {
    asm volatile("mma.sync.aligned.m16n8k16.row.col.f32.bf16.bf16.f32 "
        "{%0,%1,%2,%3}, {%4,%5,%6,%7}, {%8,%9}, {%0,%1,%2,%3};"
        : "+f"(d[0]), "+f"(d[1]), "+f"(d[2]), "+f"(d[3])
        : "r"(a[0]), "r"(a[1]), "r"(a[2]), "r"(a[3]), "r"(b0), "r"(b1));
}
// pack {lo, hi} floats -> bf16x2 (lo lands in low 16 bits), round-nearest
__device__ __forceinline__ uint32_t packbf(float lo, float hi) {
    uint32_t r;
    asm("cvt.rn.bf16x2.f32 %0, %1, %2;" : "=r"(r) : "f"(hi), "f"(lo));
    return r;
}
// truncation hi-pack: {top16(x0) in low half, top16(x1) in high half}
__device__ __forceinline__ uint32_t packbf_trunc(uint32_t u0, uint32_t u1) {
    uint32_t r;
    asm("prmt.b32 %0, %1, %2, 0x7632;" : "=r"(r) : "r"(u0), "r"(u1));
    return r;
}

// split a float pair into truncated bf16 hi pair + rounded bf16 lo pair
__device__ __forceinline__ void split2(float x0, float x1, uint32_t& hp, uint32_t& lp) {
    uint32_t u0 = __float_as_uint(x0), u1 = __float_as_uint(x1);
    hp = packbf_trunc(u0, u1);
    float l0 = x0 - __uint_as_float(u0 & 0xFFFF0000u);
    float l1 = x1 - __uint_as_float(u1 & 0xFFFF0000u);
    lp = packbf(l0, l1);
}

// ---------------- prep: fp32 bulk -> bf16 hi/lo tiles (normal + transposed) ----------------
__global__ void prep_kernel(const float* __restrict__ bulk) {
    int s = blockIdx.x;
    const float* base = bulk + s * 2048;             // [d][c][e]
    for (int idx = threadIdx.x; idx < 8192; idx += blockDim.x) {
        int tr   = idx >> 12;                        // 0 = normal, 1 = transposed
        int t    = (idx >> 10) & 3;                  // 0=M0h 1=M0l 2=Dh 3=Dl
        int half = t & 1;
        int rem  = idx & 1023;
        int n    = rem >> 5;
        int k    = rem & 31;
        float m0, m1;
        if (!tr) { m0 = base[(k * 2 + 0) * 32 + n]; m1 = base[(k * 2 + 1) * 32 + n]; }
        else     { m0 = base[(n * 2 + 0) * 32 + k]; m1 = base[(n * 2 + 1) * 32 + k]; }
        float x = (t >> 1) ? (m1 - m0) : m0;
        __nv_bfloat16 bh = __float2bfloat16(x);
        __nv_bfloat16 v  = half ? __float2bfloat16(x - __bfloat162float(bh)) : bh;
        unsigned char* arr = tr ? g_btilesT : g_btiles;
        *(__nv_bfloat16*)(arr + (size_t)s * SITE_BYTES + t * TILE_BYTES + n * ROWB + k * 2) = v;
    }
}

// ---------------- main kernel ----------------
// Warps 0,1: LEFT chain (sites 1..31). Warps 2,3: RIGHT chain (sites 62..32, transposed tiles).
// Warp w and warp w+2 cover the same 32 samples; psi = u . v joined via SMEM.
__global__ void __launch_bounds__(TPB, 4)
mps_mma_kernel(const int*   __restrict__ conf,
               const float* __restrict__ left,
               const float* __restrict__ right,
               float*       __restrict__ out)
{
    __shared__ __align__(16) unsigned char sb[2][NBUF][SITE_BYTES];   // per-pair rings
    __shared__ unsigned long long masks_s[SAMP_CTA];
    __shared__ float lt_s[64];
    __shared__ float rt_s[64];

    const int tid   = threadIdx.x;
    const int wid   = tid >> 5;
    const int lane  = tid & 31;
    const int rowq  = lane >> 2;
    const int q     = lane & 3;
    const int pair  = wid >> 1;        // 0 = left pair, 1 = right pair
    const int isR   = pair;
    const int sgrp  = wid & 1;         // sample group within CTA
    const int bid   = 1 + pair;        // named barrier id
    const int ptid  = tid & 63;

    unsigned char* ring = &sb[pair][0][0];
    const unsigned char* tbase = isR ? g_btilesT : g_btiles;

    if (tid < 64) { lt_s[tid] = left[tid]; rt_s[tid] = right[tid]; }

    if (tid < SAMP_CTA) {
        unsigned long long mask = 0;
        const int4* cp4 = (const int4*)(conf + (size_t)(blockIdx.x * SAMP_CTA + tid) * NSITES);
        #pragma unroll
        for (int i = 0; i < NSITES / 4; i++) {
            int4 v = cp4[i];
            mask |= ((unsigned long long)(v.x & 1) << (4 * i))
                  | ((unsigned long long)(v.y & 1) << (4 * i + 1))
                  | ((unsigned long long)(v.z & 1) << (4 * i + 2))
                  | ((unsigned long long)(v.w & 1) << (4 * i + 3));
        }
        masks_s[tid] = mask;
    }

    // issue G_0: tiles for iteration 0 into buffer 0
    {
        int sidx0 = isR ? (NBULK - 1) : 0;           // 61 or 0
        uint32_t dst = smem_u32(ring);
        const unsigned char* src = tbase + (size_t)sidx0 * SITE_BYTES;
        #pragma unroll
        for (int i = 0; i < 10; i++)
            cp_async16(dst + (ptid + i * 64) * 16, src + (ptid + i * 64) * 16);
        cp_commit();
    }
    __syncthreads();   // masks_s, lt_s, rt_s visible

    unsigned long long mr[4];
    #pragma unroll
    for (int k = 0; k < 4; k++) mr[k] = masks_s[sgrp * 32 + rowq + 8 * k];

    // ---- initial env as bf16 hi/lo A fragments ----
    // left: u[e] = left[c0][e];  right: v[d] = right[d][c63]
    uint32_t ah[2][4], al[2][4];       // flattened [kt][reg] pairs for i via helper below
    uint32_t ah1[2][4], al1[2][4];     // second m-tile (i=1)
    {
        #pragma unroll
        for (int i = 0; i < 2; i++) {
            const int cA = isR ? (int)(mr[2 * i] >> 63)     : (int)(mr[2 * i] & 1ull);
            const int cB = isR ? (int)(mr[2 * i + 1] >> 63) : (int)(mr[2 * i + 1] & 1ull);
            #pragma unroll
            for (int kt = 0; kt < 2; kt++)
                #pragma unroll
                for (int h = 0; h < 2; h++) {
                    int k0 = 16 * kt + 8 * h + 2 * q;
                    float xA0, xA1, xB0, xB1;
                    if (isR) {
                        xA0 = rt_s[k0 * 2 + cA];       xA1 = rt_s[(k0 + 1) * 2 + cA];
                        xB0 = rt_s[k0 * 2 + cB];       xB1 = rt_s[(k0 + 1) * 2 + cB];
                    } else {
                        xA0 = lt_s[cA * 32 + k0];      xA1 = lt_s[cA * 32 + k0 + 1];
                        xB0 = lt_s[cB * 32 + k0];      xB1 = lt_s[cB * 32 + k0 + 1];
                    }
                    uint32_t hA, lA, hB, lB;
                    split2(xA0, xA1, hA, lA);
                    split2(xB0, xB1, hB, lB);
                    // interleave: even reg -> rowA, odd -> rowB (A-frag row mapping)
                    uint32_t* AH = (i == 0) ? ah[kt] : ah1[kt];
                    uint32_t* AL = (i == 0) ? al[kt] : al1[kt];
                    AH[2 * h]     = hA;  AH[2 * h + 1] = hB;
                    AL[2 * h]     = lA;  AL[2 * h + 1] = lB;
                }
        }
    }

    const uint32_t lds_off = (uint32_t)((lane & 7) * ROWB + (lane >> 3) * 16);
    float acc[2][4][4];

    for (int t = 0; t < NHALF; t++) {
        // issue G_{t+1}
        if (t + 1 < NHALF) {
            int sidx = isR ? (NBULK - 2 - t) : (t + 1);
            uint32_t dst = smem_u32(ring + ((t + 1) & 1) * SITE_BYTES);
            const unsigned char* src = tbase + (size_t)sidx * SITE_BYTES;
            #pragma unroll
            for (int i = 0; i < 10; i++)
                cp_async16(dst + (ptid + i * 64) * 16, src + (ptid + i * 64) * 16);
            cp_commit();
            cp_wait<1>();   // G_t complete (own chunks)
        } else {
            cp_wait<0>();
        }
        pair_bar(bid);      // partner's G_t wait done -> buffer t&1 fully visible

        #pragma unroll
        for (int i = 0; i < 2; i++)
            #pragma unroll
            for (int j = 0; j < 4; j++)
                #pragma unroll
                for (int r = 0; r < 4; r++) acc[i][j][r] = 0.0f;

        const uint32_t sbase = smem_u32(ring + (t & 1) * SITE_BYTES);

        // ---- pass 1: acc += E * M0 ----
        #pragma unroll
        for (int j = 0; j < 4; j++) {
            uint32_t bh[4], bl[4];
            ldsm_x4(bh, sbase + 0 * TILE_BYTES + (uint32_t)(8 * j) * ROWB + lds_off);
            ldsm_x4(bl, sbase + 1 * TILE_BYTES + (uint32_t)(8 * j) * ROWB + lds_off);
            mma16816(acc[0][j], ah[0],  bh[0], bh[1]);
            mma16816(acc[0][j], ah[1],  bh[2], bh[3]);
            mma16816(acc[0][j], al[0],  bh[0], bh[1]);
            mma16816(acc[0][j], al[1],  bh[2], bh[3]);
            mma16816(acc[0][j], ah[0],  bl[0], bl[1]);
            mma16816(acc[0][j], ah[1],  bl[2], bl[3]);
            mma16816(acc[1][j], ah1[0], bh[0], bh[1]);
            mma16816(acc[1][j], ah1[1], bh[2], bh[3]);
            mma16816(acc[1][j], al1[0], bh[0], bh[1]);
            mma16816(acc[1][j], al1[1], bh[2], bh[3]);
            mma16816(acc[1][j], ah1[0], bl[0], bl[1]);
            mma16816(acc[1][j], ah1[1], bl[2], bl[3]);
        }

        // ---- mask A fragments in place with this site's config bit ----
        {
            const int bitpos = isR ? (62 - t) : (t + 1);
            const uint32_t c0 = (uint32_t)((mr[0] >> bitpos) & 1ull);
            const uint32_t c1 = (uint32_t)((mr[1] >> bitpos) & 1ull);
            const uint32_t c2 = (uint32_t)((mr[2] >> bitpos) & 1ull);
            const uint32_t c3 = (uint32_t)((mr[3] >> bitpos) & 1ull);
            #pragma unroll
            for (int kt = 0; kt < 2; kt++)
                #pragma unroll
                for (int h = 0; h < 2; h++) {
                    ah[kt][2*h]    = c0 ? ah[kt][2*h]    : 0u;
                    al[kt][2*h]    = c0 ? al[kt][2*h]    : 0u;
                    ah[kt][2*h+1]  = c1 ? ah[kt][2*h+1]  : 0u;
                    al[kt][2*h+1]  = c1 ? al[kt][2*h+1]  : 0u;
                    ah1[kt][2*h]   = c2 ? ah1[kt][2*h]   : 0u;
                    al1[kt][2*h]   = c2 ? al1[kt][2*h]   : 0u;
                    ah1[kt][2*h+1] = c3 ? ah1[kt][2*h+1] : 0u;
                    al1[kt][2*h+1] = c3 ? al1[kt][2*h+1] : 0u;
                }
        }

        // ---- pass 2: acc += E_masked * Delta ----
        #pragma unroll
        for (int j = 0; j < 4; j++) {
            uint32_t bh[4], bl[4];
            ldsm_x4(bh, sbase + 2 * TILE_BYTES + (uint32_t)(8 * j) * ROWB + lds_off);
            ldsm_x4(bl, sbase + 3 * TILE_BYTES + (uint32_t)(8 * j) * ROWB + lds_off);
            mma16816(acc[0][j], ah[0],  bh[0], bh[1]);
            mma16816(acc[0][j], ah[1],  bh[2], bh[3]);
            mma16816(acc[0][j], al[0],  bh[0], bh[1]);
            mma16816(acc[0][j], al[1],  bh[2], bh[3]);
            mma16816(acc[0][j], ah[0],  bl[0], bl[1]);
            mma16816(acc[0][j], ah[1],  bl[2], bl[3]);
            mma16816(acc[1][j], ah1[0], bh[0], bh[1]);
            mma16816(acc[1][j], ah1[1], bh[2], bh[3]);
            mma16816(acc[1][j], al1[0], bh[0], bh[1]);
            mma16816(acc[1][j], al1[1], bh[2], bh[3]);
            mma16816(acc[1][j], ah1[0], bl[0], bl[1]);
            mma16816(acc[1][j], ah1[1], bl[2], bl[3]);
        }

        // ---- split env (acc) -> next A fragments (D-layout == A-layout) ----
        if (t + 1 < NHALF) {
            #pragma unroll
            for (int i = 0; i < 2; i++)
                #pragma unroll
                for (int kt = 0; kt < 2; kt++)
                    #pragma unroll
                    for (int h = 0; h < 2; h++) {
                        float x0 = acc[i][2 * kt + h][0], x1 = acc[i][2 * kt + h][1];
                        float x2 = acc[i][2 * kt + h][2], x3 = acc[i][2 * kt + h][3];
                        uint32_t hA, lA, hB, lB;
                        split2(x0, x1, hA, lA);
                        split2(x2, x3, hB, lB);
                        uint32_t* AH = (i == 0) ? ah[kt] : ah1[kt];
                        uint32_t* AL = (i == 0) ? al[kt] : al1[kt];
                        AH[2 * h]     = hA;  AH[2 * h + 1] = hB;
                        AL[2 * h]     = lA;  AL[2 * h + 1] = lB;
                    }
        }
        pair_bar(bid);   // both warps done reading buf t&1 -> next issue may overwrite
    }

    // ---- join: psi = u . v ----
    float* vbuf = (float*)&sb[1][0][0];   // alias right pair's ring (dead now)
    if (isR) {
        #pragma unroll
        for (int i = 0; i < 2; i++)
            #pragma unroll
            for (int j = 0; j < 4; j++)
                #pragma unroll
                for (int r = 0; r < 4; r++) {
                    int row = sgrp * 32 + rowq + 16 * i + 8 * (r >> 1);
                    int col = 8 * j + 2 * q + (r & 1);
                    vbuf[row * 32 + col] = acc[i][j][r];
                }
    }
    __syncthreads();
    if (!isR) {
        float p[4];
        #pragma unroll
        for (int i = 0; i < 2; i++) {
            #pragma unroll
            for (int b = 0; b < 2; b++) {
                int row = sgrp * 32 + rowq + 16 * i + 8 * b;
                float s = 0.0f;
                #pragma unroll
                for (int j = 0; j < 4; j++) {
                    int col = 8 * j + 2 * q;
                    s += acc[i][j][2 * b]     * vbuf[row * 32 + col]
                       + acc[i][j][2 * b + 1] * vbuf[row * 32 + col + 1];
                }
                p[2 * i + b] = s;
            }
        }
        #pragma unroll
        for (int k = 0; k < 4; k++) {
            p[k] += __shfl_xor_sync(0xFFFFFFFF, p[k], 1);
            p[k] += __shfl_xor_sync(0xFFFFFFFF, p[k], 2);
        }
        if (q == 0) {
            int base = blockIdx.x * SAMP_CTA + sgrp * 32 + rowq;
            #pragma unroll
            for (int k = 0; k < 4; k++) out[base + 8 * k] = p[k];
        }
    }
}

extern "C" void kernel_launch(void* const* d_in, const int* in_sizes, int n_in,
                              void* d_out, int out_size) {
    const int*   conf  = (const int*)d_in[0];
    const float* left  = (const float*)d_in[1];
    const float* bulk  = (const float*)d_in[2];
    const float* right = (const float*)d_in[3];
    float*       out   = (float*)d_out;

    prep_kernel<<<NBULK, 256>>>(bulk);
    mps_mma_kernel<<<NCTA, TPB>>>(conf, left, right, out);
}

// round 9
// speedup vs baseline: 1.1913x; 1.1087x over previous
#include <cuda_runtime.h>
#include <cuda_bf16.h>
#include <cstdint>

#define BATCH   32768
#define NSITES  64
#define NBULK   62
#define TPB     128
#define SAMP_CTA 128                   // 4 warps x 32 samples
#define NCTA    (BATCH / SAMP_CTA)     // 256

// Fragment-linear B operands: [site][pass(4)][j(4)][lane(32)] x 16B.
// pass: 0=M0h, 1=M0l, 2=Dh, 3=Dl. One extra site of slop for the s+1 prefetch.
__device__ __align__(256) uint4 g_bfrags[(NBULK + 1) * 4 * 4 * 32];

// ---------------- helpers ----------------
__device__ __forceinline__ void mma16816(float* d, const uint32_t* a, uint32_t b0, uint32_t b1) {
    asm volatile("mma.sync.aligned.m16n8k16.row.col.f32.bf16.bf16.f32 "
        "{%0,%1,%2,%3}, {%4,%5,%6,%7}, {%8,%9}, {%0,%1,%2,%3};"
        : "+f"(d[0]), "+f"(d[1]), "+f"(d[2]), "+f"(d[3])
        : "r"(a[0]), "r"(a[1]), "r"(a[2]), "r"(a[3]), "r"(b0), "r"(b1));
}
// first MMA of an accumulator: D = A*B + Z (Z = persistent zeros), no pre-zeroing
__device__ __forceinline__ void mma16816_z(float* d, const uint32_t* a, uint32_t b0, uint32_t b1,
                                           const float* z) {
    asm volatile("mma.sync.aligned.m16n8k16.row.col.f32.bf16.bf16.f32 "
        "{%0,%1,%2,%3}, {%4,%5,%6,%7}, {%8,%9}, {%10,%11,%12,%13};"
        : "=f"(d[0]), "=f"(d[1]), "=f"(d[2]), "=f"(d[3])
        : "r"(a[0]), "r"(a[1]), "r"(a[2]), "r"(a[3]), "r"(b0), "r"(b1),
          "f"(z[0]), "f"(z[1]), "f"(z[2]), "f"(z[3]));
}
__device__ __forceinline__ uint32_t packbf(float lo, float hi) {
    uint32_t r;
    asm("cvt.rn.bf16x2.f32 %0, %1, %2;" : "=r"(r) : "f"(hi), "f"(lo));
    return r;
}
__device__ __forceinline__ uint32_t packbf_trunc(uint32_t u0, uint32_t u1) {
    uint32_t r;
    asm("prmt.b32 %0, %1, %2, 0x7632;" : "=r"(r) : "r"(u0), "r"(u1));
    return r;
}
__device__ __forceinline__ void split2(float x0, float x1, uint32_t& hp, uint32_t& lp) {
    uint32_t u0 = __float_as_uint(x0), u1 = __float_as_uint(x1);
    hp = packbf_trunc(u0, u1);
    float l0 = x0 - __uint_as_float(u0 & 0xFFFF0000u);
    float l1 = x1 - __uint_as_float(u1 & 0xFFFF0000u);
    lp = packbf(l0, l1);
}

// ---------------- prep: fp32 bulk -> fragment-linear bf16 hi/lo B operands ----------------
// Fragment mapping (replicating SMEM[n][k] + ldmatrix.m8n8.x4 composite):
//   reg m of lane l for block j = bf16 pair ( M[k][n], M[k+1][n] ),
//   n = 8*j + (l>>2),  k = 8*m + 2*(l&3).
__global__ void prep_kernel(const float* __restrict__ bulk) {
    int s = blockIdx.x;
    const float* base = bulk + s * 2048;            // [d][c][e]
    for (int idx = threadIdx.x; idx < 2048; idx += blockDim.x) {
        int pass = idx >> 9;                         // 0..3
        int j    = (idx >> 7) & 3;
        int lane = (idx >> 2) & 31;
        int m    = idx & 3;
        int n    = 8 * j + (lane >> 2);
        int k    = 8 * m + 2 * (lane & 3);
        float v0, v1;
        {
            float a0 = base[(k * 2 + 0) * 32 + n];
            float b0 = base[(k * 2 + 1) * 32 + n];
            float a1 = base[((k + 1) * 2 + 0) * 32 + n];
            float b1 = base[((k + 1) * 2 + 1) * 32 + n];
            float x0 = (pass >= 2) ? (b0 - a0) : a0;
            float x1 = (pass >= 2) ? (b1 - a1) : a1;
            if (pass & 1) {   // lo halves
                __nv_bfloat16 h0 = __float2bfloat16(x0);
                __nv_bfloat16 h1 = __float2bfloat16(x1);
                v0 = x0 - __bfloat162float(h0);
                v1 = x1 - __bfloat162float(h1);
            } else {
                v0 = x0; v1 = x1;
            }
        }
        uint32_t pair = packbf(v0, v1);   // low half = lower-k element
        ((uint32_t*)g_bfrags)[(((s * 4 + pass) * 4 + j) * 32 + lane) * 4 + m] = pair;
    }
}

// ---------------- main kernel ----------------
// M=32 per warp, barrier-free mainloop, B operands via LDG.128 fragment loads.
__global__ void __launch_bounds__(TPB)
mps_mma_kernel(const int*   __restrict__ conf,
               const float* __restrict__ left,
               const float* __restrict__ right,
               float*       __restrict__ out)
{
    __shared__ unsigned long long masks_s[SAMP_CTA];
    __shared__ float lt_s[64];
    __shared__ float rt_s[64];

    const int tid  = threadIdx.x;
    const int wid  = tid >> 5;
    const int lane = tid & 31;
    const int rowq = lane >> 2;
    const int q    = lane & 3;

    if (tid < 64) { lt_s[tid] = left[tid]; rt_s[tid] = right[tid]; }

    {
        unsigned long long mask = 0;
        const int4* cp4 = (const int4*)(conf + (size_t)(blockIdx.x * SAMP_CTA + tid) * NSITES);
        #pragma unroll
        for (int i = 0; i < NSITES / 4; i++) {
            int4 v = cp4[i];
            mask |= ((unsigned long long)(v.x & 1) << (4 * i))
                  | ((unsigned long long)(v.y & 1) << (4 * i + 1))
                  | ((unsigned long long)(v.z & 1) << (4 * i + 2))
                  | ((unsigned long long)(v.w & 1) << (4 * i + 3));
        }
        masks_s[tid] = mask;
    }
    __syncthreads();   // the ONLY block barrier before the epilogue

    unsigned long long mr[4];
    #pragma unroll
    for (int k = 0; k < 4; k++) mr[k] = masks_s[wid * 32 + rowq + 8 * k];

    // ---- initial env = left[c0] as bf16 hi/lo A fragments ----
    uint32_t ah[2][2][4], al[2][2][4];   // [mtile][kt][reg]
    #pragma unroll
    for (int i = 0; i < 2; i++) {
        const int cA = (int)(mr[2 * i] & 1ull);
        const int cB = (int)(mr[2 * i + 1] & 1ull);
        #pragma unroll
        for (int kt = 0; kt < 2; kt++)
            #pragma unroll
            for (int h = 0; h < 2; h++) {
                int k0 = 16 * kt + 8 * h + 2 * q;
                uint32_t hA, lA, hB, lB;
                split2(lt_s[cA * 32 + k0], lt_s[cA * 32 + k0 + 1], hA, lA);
                split2(lt_s[cB * 32 + k0], lt_s[cB * 32 + k0 + 1], hB, lB);
                ah[i][kt][2 * h]     = hA;  ah[i][kt][2 * h + 1] = hB;
                al[i][kt][2 * h]     = lA;  al[i][kt][2 * h + 1] = lB;
            }
    }

    // per-lane fragment pointer: g_bfrags + (((s*4 + pass)*4 + j)*32 + lane)
    const uint4* fb = g_bfrags + lane;

    // prologue: load site 0, passes 0-1 (M0 hi+lo), 8 x LDG.128
    uint4 bA[8], bB[8];
    #pragma unroll
    for (int j = 0; j < 4; j++) {
        bA[j]     = __ldg(fb + ((0 * 4 + 0) * 4 + j) * 32);
        bA[4 + j] = __ldg(fb + ((0 * 4 + 1) * 4 + j) * 32);
    }

    const float z4[4] = {0.0f, 0.0f, 0.0f, 0.0f};
    float acc[2][4][4];

    for (int s = 0; s < NBULK; s++) {
        // issue Δ-pass loads for site s (consumed after pass 1)
        #pragma unroll
        for (int j = 0; j < 4; j++) {
            bB[j]     = __ldg(fb + (((s * 4 + 2) * 4) + j) * 32);
            bB[4 + j] = __ldg(fb + (((s * 4 + 3) * 4) + j) * 32);
        }

        // ---- pass 1: acc = E * M0 (3 precision terms), first MMA consumes z4 ----
        #pragma unroll
        for (int j = 0; j < 4; j++) {
            #pragma unroll
            for (int i = 0; i < 2; i++) {
                float* a = acc[i][j];
                mma16816_z(a, ah[i][0], bA[j].x, bA[j].y, z4);
                mma16816(a, ah[i][1], bA[j].z, bA[j].w);
                mma16816(a, al[i][0], bA[j].x, bA[j].y);
                mma16816(a, al[i][1], bA[j].z, bA[j].w);
                mma16816(a, ah[i][0], bA[4 + j].x, bA[4 + j].y);
                mma16816(a, ah[i][1], bA[4 + j].z, bA[4 + j].w);
            }
        }

        // ---- mask A fragments in place with site-(s+1) bits ----
        {
            const uint32_t c0 = (uint32_t)((mr[0] >> (s + 1)) & 1ull);
            const uint32_t c1 = (uint32_t)((mr[1] >> (s + 1)) & 1ull);
            const uint32_t c2 = (uint32_t)((mr[2] >> (s + 1)) & 1ull);
            const uint32_t c3 = (uint32_t)((mr[3] >> (s + 1)) & 1ull);
            #pragma unroll
            for (int kt = 0; kt < 2; kt++)
                #pragma unroll
                for (int h = 0; h < 2; h++) {
                    ah[0][kt][2*h]   = c0 ? ah[0][kt][2*h]   : 0u;
                    al[0][kt][2*h]   = c0 ? al[0][kt][2*h]   : 0u;
                    ah[0][kt][2*h+1] = c1 ? ah[0][kt][2*h+1] : 0u;
                    al[0][kt][2*h+1] = c1 ? al[0][kt][2*h+1] : 0u;
                    ah[1][kt][2*h]   = c2 ? ah[1][kt][2*h]   : 0u;
                    al[1][kt][2*h]   = c2 ? al[1][kt][2*h]   : 0u;
                    ah[1][kt][2*h+1] = c3 ? ah[1][kt][2*h+1] : 0u;
                    al[1][kt][2*h+1] = c3 ? al[1][kt][2*h+1] : 0u;
                }
        }

        // issue next site's M0-pass loads (consumed next iteration)
        if (s + 1 < NBULK) {
            #pragma unroll
            for (int j = 0; j < 4; j++) {
                bA[j]     = __ldg(fb + ((((s + 1) * 4 + 0) * 4) + j) * 32);
                bA[4 + j] = __ldg(fb + ((((s + 1) * 4 + 1) * 4) + j) * 32);
            }
        }

        // ---- pass 2: acc += E_masked * Delta (3 precision terms) ----
        #pragma unroll
        for (int j = 0; j < 4; j++) {
            #pragma unroll
            for (int i = 0; i < 2; i++) {
                float* a = acc[i][j];
                mma16816(a, ah[i][0], bB[j].x, bB[j].y);
                mma16816(a, ah[i][1], bB[j].z, bB[j].w);
                mma16816(a, al[i][0], bB[j].x, bB[j].y);
                mma16816(a, al[i][1], bB[j].z, bB[j].w);
                mma16816(a, ah[i][0], bB[4 + j].x, bB[4 + j].y);
                mma16816(a, ah[i][1], bB[4 + j].z, bB[4 + j].w);
            }
        }

        // ---- split selected env (acc) -> next A fragments ----
        if (s + 1 < NBULK) {
            #pragma unroll
            for (int i = 0; i < 2; i++)
                #pragma unroll
                for (int kt = 0; kt < 2; kt++)
                    #pragma unroll
                    for (int h = 0; h < 2; h++) {
                        uint32_t hA, lA, hB, lB;
                        split2(acc[i][2 * kt + h][0], acc[i][2 * kt + h][1], hA, lA);
                        split2(acc[i][2 * kt + h][2], acc[i][2 * kt + h][3], hB, lB);
                        ah[i][kt][2 * h]     = hA;  ah[i][kt][2 * h + 1] = hB;
                        al[i][kt][2 * h]     = lA;  al[i][kt][2 * h + 1] = lB;
                    }
        }
    }

    // ---- final dot with right[:, c63]; reduce across the 4 lanes of each row group ----
    float p[4];
    #pragma unroll
    for (int i = 0; i < 2; i++) {
        const int cA = (int)(mr[2 * i]     >> 63);
        const int cB = (int)(mr[2 * i + 1] >> 63);
        float pa = 0.0f, pb = 0.0f;
        #pragma unroll
        for (int j = 0; j < 4; j++) {
            int n0 = 8 * j + 2 * q;
            pa += acc[i][j][0] * rt_s[n0 * 2 + cA] + acc[i][j][1] * rt_s[(n0 + 1) * 2 + cA];
            pb += acc[i][j][2] * rt_s[n0 * 2 + cB] + acc[i][j][3] * rt_s[(n0 + 1) * 2 + cB];
        }
        p[2 * i]     = pa;
        p[2 * i + 1] = pb;
    }
    #pragma unroll
    for (int k = 0; k < 4; k++) {
        p[k] += __shfl_xor_sync(0xFFFFFFFF, p[k], 1);
        p[k] += __shfl_xor_sync(0xFFFFFFFF, p[k], 2);
    }
    if (q == 0) {
        int base = blockIdx.x * SAMP_CTA + wid * 32 + rowq;
        #pragma unroll
        for (int k = 0; k < 4; k++) out[base + 8 * k] = p[k];
    }
}

extern "C" void kernel_launch(void* const* d_in, const int* in_sizes, int n_in,
                              void* d_out, int out_size) {
    const int*   conf  = (const int*)d_in[0];
    const float* left  = (const float*)d_in[1];
    const float* bulk  = (const float*)d_in[2];
    const float* right = (const float*)d_in[3];
    float*       out   = (float*)d_out;

    prep_kernel<<<NBULK, 256>>>(bulk);
    mps_mma_kernel<<<NCTA, TPB>>>(conf, left, right, out);
}